// round 10
// baseline (speedup 1.0000x reference)
#include <cuda_runtime.h>
#include <cstdint>

#define THREADS 256
#define M_TILE  128

// ---------------- SMEM layout (bytes) ----------------
// X half-buffers: 128 rows x 32 bf16 (64B rows, SW64), hi+lo, double-buffered
#define OFF_B1    0
#define OFF_B2    256
#define OFF_XA_HI 1024
#define OFF_XA_LO (OFF_XA_HI + 8192)     //  9216
#define OFF_XB_HI (OFF_XA_HI + 16384)    // 17408
#define OFF_XB_LO (OFF_XA_HI + 24576)    // 25600
#define OFF_W1HI  33792                   // 192 x 64 bf16, 128B rows, SW128
#define OFF_W1LO  (OFF_W1HI + 24576)     // 58368
#define OFF_W2HI  (OFF_W1LO + 24576)     // 82944
#define OFF_W2LO  (OFF_W2HI + 8192)      // 91136
#define SMEM_BYTES (OFF_W2LO + 8192)     // 99328 -> 2 CTAs/SM

// ---------------- helpers ----------------
__device__ __forceinline__ uint32_t smem_u32(const void* p) {
    uint32_t a;
    asm("{ .reg .u64 t; cvta.to.shared.u64 t, %1; cvt.u32.u64 %0, t; }" : "=r"(a) : "l"(p));
    return a;
}
__device__ __forceinline__ uint32_t sw128(uint32_t o) { return o ^ ((o >> 3) & 0x70); }
__device__ __forceinline__ uint32_t sw64(uint32_t o)  { return o ^ ((o >> 3) & 0x30); }

__device__ __forceinline__ uint32_t pack2bf(float e0, float e1) {
    uint32_t r;
    asm("cvt.rn.bf16x2.f32 %0, %1, %2;" : "=r"(r) : "f"(e1), "f"(e0));
    return r;
}

// split 4 fp32 into bf16 hi/lo, 8B store each
__device__ __forceinline__ void split_store(char* hip, char* lop, float4 v) {
    uint32_t h01 = pack2bf(v.x, v.y);
    uint32_t h23 = pack2bf(v.z, v.w);
    float f0 = __uint_as_float(h01 << 16);
    float f1 = __uint_as_float(h01 & 0xFFFF0000u);
    float f2 = __uint_as_float(h23 << 16);
    float f3 = __uint_as_float(h23 & 0xFFFF0000u);
    uint32_t l01 = pack2bf(v.x - f0, v.y - f1);
    uint32_t l23 = pack2bf(v.z - f2, v.w - f3);
    *reinterpret_cast<uint2*>(hip) = make_uint2(h01, h23);
    *reinterpret_cast<uint2*>(lop) = make_uint2(l01, l23);
}

__device__ __forceinline__ void ldsm4(uint32_t r[4], uint32_t addr) {
    asm volatile("ldmatrix.sync.aligned.m8n8.x4.shared.b16 {%0,%1,%2,%3}, [%4];"
        : "=r"(r[0]), "=r"(r[1]), "=r"(r[2]), "=r"(r[3]) : "r"(addr));
}
__device__ __forceinline__ void ldsm4t(uint32_t r[4], uint32_t addr) {
    asm volatile("ldmatrix.sync.aligned.m8n8.x4.trans.shared.b16 {%0,%1,%2,%3}, [%4];"
        : "=r"(r[0]), "=r"(r[1]), "=r"(r[2]), "=r"(r[3]) : "r"(addr));
}
__device__ __forceinline__ void mma16816(float c[4], const uint32_t a[4], const uint32_t b[2]) {
    asm volatile(
        "mma.sync.aligned.m16n8k16.row.col.f32.bf16.bf16.f32 "
        "{%0,%1,%2,%3}, {%4,%5,%6,%7}, {%8,%9}, {%0,%1,%2,%3};"
        : "+f"(c[0]), "+f"(c[1]), "+f"(c[2]), "+f"(c[3])
        : "r"(a[0]), "r"(a[1]), "r"(a[2]), "r"(a[3]), "r"(b[0]), "r"(b[1]));
}
// weight (128B-row SW128) fragment address
__device__ __forceinline__ uint32_t frag_w(uint32_t base, int rbase, int cbase, int lane) {
    int row  = rbase + (lane & 15);
    int colb = cbase * 2 + (lane & 16);
    return base + sw128((uint32_t)(row * 128 + colb));
}
// X (64B-row SW64) fragment address
__device__ __forceinline__ uint32_t frag_x(uint32_t base, int rbase, int kk, int lane) {
    int row  = rbase + (lane & 15);
    int colb = kk * 2 + (lane & 16);
    return base + sw64((uint32_t)(row * 64 + colb));
}
__device__ __forceinline__ void prefetch_l2(const void* p) {
    asm volatile("prefetch.global.L2 [%0];" :: "l"(p));
}
__device__ __forceinline__ void sched_fence() {
    asm volatile("" ::: "memory");
}

__global__ __launch_bounds__(THREADS, 2)
void edge_mlp_mma(const float* __restrict__ src, const float* __restrict__ dst,
                  const float* __restrict__ ea,
                  const float* __restrict__ W1, const float* __restrict__ b1,
                  const float* __restrict__ W2, const float* __restrict__ b2,
                  float* __restrict__ out, int E, int ntiles)
{
    extern __shared__ char smem[];
    const uint32_t sb = smem_u32(smem);
    const int tid = threadIdx.x;
    const int lid = tid & 31;
    const int wid = tid >> 5;

    const int wm = wid & 3;   // M group: rows 32*wm .. +31
    const int wn = wid >> 2;  // N group: cols 32*wn .. +31

    // ================= ONE-TIME: biases + weights =================
    if (tid < 64) {
        ((float*)(smem + OFF_B1))[tid] = b1[tid];
        ((float*)(smem + OFF_B2))[tid] = b2[tid];
    }
    #pragma unroll
    for (int i = 0; i < 12; ++i) {
        int idx = tid + i * THREADS;
        uint32_t off = sw128((uint32_t)((idx >> 4) * 128 + (idx & 15) * 8));
        float4 v = ((const float4*)W1)[idx];
        split_store(smem + OFF_W1HI + off, smem + OFF_W1LO + off, v);
    }
    #pragma unroll
    for (int i = 0; i < 4; ++i) {
        int idx = tid + i * THREADS;
        uint32_t off = sw128((uint32_t)((idx >> 4) * 128 + (idx & 15) * 8));
        float4 v = ((const float4*)W2)[idx];
        split_store(smem + OFF_W2HI + off, smem + OFF_W2LO + off, v);
    }

    float acc[2][4][4];
    #pragma unroll
    for (int mt = 0; mt < 2; ++mt)
        #pragma unroll
        for (int nt = 0; nt < 4; ++nt)
            #pragma unroll
            for (int j = 0; j < 4; ++j) acc[mt][nt][j] = 0.f;

    // ---- load one 32-k half of a segment into registers (MLP=4) ----
    auto load_half = [&](const float* __restrict__ p, int e0, int half, float4* v) {
        #pragma unroll
        for (int i = 0; i < 4; ++i) {
            int idx = tid + i * THREADS;           // 0..1023
            int e = e0 + (idx >> 3);
            v[i] = (e < E) ? ((const float4*)p)[(size_t)e * 16 + half * 8 + (idx & 7)]
                           : make_float4(0.f, 0.f, 0.f, 0.f);
        }
    };
    // ---- split + store a half-buffer (64B rows, SW64) ----
    auto store_half = [&](uint32_t hio, uint32_t loo, const float4* v) {
        #pragma unroll
        for (int i = 0; i < 4; ++i) {
            int idx = tid + i * THREADS;
            uint32_t off = sw64((uint32_t)((idx >> 3) * 64 + (idx & 7) * 8));
            split_store(smem + hio + off, smem + loo + off, v[i]);
        }
    };

    // one 16-wide k-step, term-major; A from 64B-row half-buffer
    auto kstep = [&](uint32_t xhi, uint32_t xlo, int kk,
                     uint32_t bhib, uint32_t blob, int kg) {
        uint32_t bhi[2][4], blo[2][4], ahi[2][4], alo[2][4];
        ldsm4t(bhi[0], frag_w(bhib, kg, wn * 32,      lid));
        ldsm4t(bhi[1], frag_w(bhib, kg, wn * 32 + 16, lid));
        ldsm4t(blo[0], frag_w(blob, kg, wn * 32,      lid));
        ldsm4t(blo[1], frag_w(blob, kg, wn * 32 + 16, lid));
        ldsm4(ahi[0], frag_x(xhi, wm * 32,      kk, lid));
        ldsm4(ahi[1], frag_x(xhi, wm * 32 + 16, kk, lid));
        ldsm4(alo[0], frag_x(xlo, wm * 32,      kk, lid));
        ldsm4(alo[1], frag_x(xlo, wm * 32 + 16, kk, lid));
        #pragma unroll
        for (int mt = 0; mt < 2; ++mt)
            #pragma unroll
            for (int nt = 0; nt < 4; ++nt)
                mma16816(acc[mt][nt], ahi[mt], &bhi[nt >> 1][(nt & 1) * 2]);
        #pragma unroll
        for (int mt = 0; mt < 2; ++mt)
            #pragma unroll
            for (int nt = 0; nt < 4; ++nt)
                mma16816(acc[mt][nt], ahi[mt], &blo[nt >> 1][(nt & 1) * 2]);
        #pragma unroll
        for (int mt = 0; mt < 2; ++mt)
            #pragma unroll
            for (int nt = 0; nt < 4; ++nt)
                mma16816(acc[mt][nt], alo[mt], &bhi[nt >> 1][(nt & 1) * 2]);
    };
    // two k-steps (one 32-k half) against weight rows kg, kg+16
    auto mma2 = [&](uint32_t xhi, uint32_t xlo, uint32_t whib, uint32_t wlob, int kg) {
        kstep(xhi, xlo, 0,  whib, wlob, kg);
        kstep(xhi, xlo, 16, whib, wlob, kg + 16);
    };

    const uint32_t XAh = sb + OFF_XA_HI, XAl = sb + OFF_XA_LO;
    const uint32_t XBh = sb + OFF_XB_HI, XBl = sb + OFF_XB_LO;
    const uint32_t W1h = sb + OFF_W1HI,  W1l = sb + OFF_W1LO;
    const uint32_t W2h = sb + OFF_W2HI,  W2l = sb + OFF_W2LO;

    // ================= persistent tile loop =================
    for (int t = blockIdx.x; t < ntiles; t += gridDim.x) {
        const int e0 = t * M_TILE;
        float4 v[4];

        // P0: stage seg0.h0 -> XA
        load_half(src, e0, 0, v);
        prefetch_l2((const char*)(dst + (size_t)e0 * 64) + (size_t)tid * 128);
        store_half(OFF_XA_HI, OFF_XA_LO, v);
        __syncthreads();
        // P1: mma XA (kg 0..31) | stage seg0.h1 -> XB
        load_half(src, e0, 1, v);
        mma2(XAh, XAl, W1h, W1l, 0);
        sched_fence();
        store_half(OFF_XB_HI, OFF_XB_LO, v);
        __syncthreads();
        // P2: mma XB (32..63) | stage seg1.h0 -> XA
        load_half(dst, e0, 0, v);
        prefetch_l2((const char*)(ea + (size_t)e0 * 64) + (size_t)tid * 128);
        mma2(XBh, XBl, W1h, W1l, 32);
        sched_fence();
        store_half(OFF_XA_HI, OFF_XA_LO, v);
        __syncthreads();
        // P3: mma XA (64..95) | stage seg1.h1 -> XB
        load_half(dst, e0, 1, v);
        mma2(XAh, XAl, W1h, W1l, 64);
        sched_fence();
        store_half(OFF_XB_HI, OFF_XB_LO, v);
        __syncthreads();
        // P4: mma XB (96..127) | stage seg2.h0 -> XA
        load_half(ea, e0, 0, v);
        {
            int tn = t + gridDim.x;
            const float* nxt = (tn < ntiles) ? src + (size_t)tn * M_TILE * 64
                                             : src + (size_t)e0 * 64;
            prefetch_l2((const char*)nxt + (size_t)tid * 128);
        }
        mma2(XBh, XBl, W1h, W1l, 96);
        sched_fence();
        store_half(OFF_XA_HI, OFF_XA_LO, v);
        __syncthreads();
        // P5: mma XA (128..159) | stage seg2.h1 -> XB
        load_half(ea, e0, 1, v);
        mma2(XAh, XAl, W1h, W1l, 128);
        sched_fence();
        store_half(OFF_XB_HI, OFF_XB_LO, v);
        __syncthreads();
        // P6: mma XB (160..191)
        mma2(XBh, XBl, W1h, W1l, 160);
        __syncthreads();

        // P7: bias1 + ReLU + split -> H  (wn=0 -> XA holds k0..31, wn=1 -> XB k32..63)
        {
            const float* b1s = (const float*)(smem + OFF_B1);
            const uint32_t hio = wn ? OFF_XB_HI : OFF_XA_HI;
            const uint32_t loo = wn ? OFF_XB_LO : OFF_XA_LO;
            #pragma unroll
            for (int mt = 0; mt < 2; ++mt)
                #pragma unroll
                for (int nt = 0; nt < 4; ++nt) {
                    int row = wm * 32 + mt * 16 + (lid >> 2);
                    int c   = nt * 8 + (lid & 3) * 2;          // local col 0..31
                    int col = wn * 32 + c;
                    float bc0 = b1s[col], bc1 = b1s[col + 1];
                    float h0 = fmaxf(acc[mt][nt][0] + bc0, 0.f);
                    float h1 = fmaxf(acc[mt][nt][1] + bc1, 0.f);
                    float h2 = fmaxf(acc[mt][nt][2] + bc0, 0.f);
                    float h3 = fmaxf(acc[mt][nt][3] + bc1, 0.f);
                    uint32_t hA = pack2bf(h0, h1);
                    uint32_t hB = pack2bf(h2, h3);
                    uint32_t lA = pack2bf(h0 - __uint_as_float(hA << 16),
                                          h1 - __uint_as_float(hA & 0xFFFF0000u));
                    uint32_t lB = pack2bf(h2 - __uint_as_float(hB << 16),
                                          h3 - __uint_as_float(hB & 0xFFFF0000u));
                    uint32_t oA = sw64((uint32_t)(row * 64 + c * 2));
                    uint32_t oB = sw64((uint32_t)((row + 8) * 64 + c * 2));
                    *(uint32_t*)(smem + hio + oA) = hA;
                    *(uint32_t*)(smem + loo + oA) = lA;
                    *(uint32_t*)(smem + hio + oB) = hB;
                    *(uint32_t*)(smem + loo + oB) = lB;
                    acc[mt][nt][0] = acc[mt][nt][1] = acc[mt][nt][2] = acc[mt][nt][3] = 0.f;
                }
        }
        __syncthreads();

        // P8: GEMM2 (K=64: XA k0..31 w/ W2 rows 0..31, XB k32..63 w/ rows 32..63)
        mma2(XAh, XAl, W2h, W2l, 0);
        mma2(XBh, XBl, W2h, W2l, 32);

        // epilogue: + bias2, float2 stores; reset acc
        {
            const float* b2s = (const float*)(smem + OFF_B2);
            #pragma unroll
            for (int mt = 0; mt < 2; ++mt)
                #pragma unroll
                for (int nt = 0; nt < 4; ++nt) {
                    int row = wm * 32 + mt * 16 + (lid >> 2);
                    int col = wn * 32 + nt * 8 + (lid & 3) * 2;
                    float bc0 = b2s[col], bc1 = b2s[col + 1];
                    int eA = e0 + row, eB = e0 + row + 8;
                    if (eA < E)
                        *(float2*)&out[(size_t)eA * 64 + col] =
                            make_float2(acc[mt][nt][0] + bc0, acc[mt][nt][1] + bc1);
                    if (eB < E)
                        *(float2*)&out[(size_t)eB * 64 + col] =
                            make_float2(acc[mt][nt][2] + bc0, acc[mt][nt][3] + bc1);
                    acc[mt][nt][0] = acc[mt][nt][1] = acc[mt][nt][2] = acc[mt][nt][3] = 0.f;
                }
        }
        __syncthreads();                           // GEMM2/H reads done before next tile stage
    }
}

extern "C" void kernel_launch(void* const* d_in, const int* in_sizes, int n_in,
                              void* d_out, int out_size)
{
    const float* src = (const float*)d_in[0];
    const float* dst = (const float*)d_in[1];
    const float* ea  = (const float*)d_in[2];
    const float* W1  = (const float*)d_in[5];
    const float* b1  = (const float*)d_in[6];
    const float* W2  = (const float*)d_in[7];
    const float* b2  = (const float*)d_in[8];
    float* out = (float*)d_out;

    int E = in_sizes[0] / 64;
    int ntiles = (E + M_TILE - 1) / M_TILE;

    cudaFuncSetAttribute(edge_mlp_mma,
                         cudaFuncAttributeMaxDynamicSharedMemorySize, SMEM_BYTES);

    int grid = 2 * 148;
    if (grid > ntiles) grid = ntiles;
    edge_mlp_mma<<<grid, THREADS, SMEM_BYTES>>>(src, dst, ea, W1, b1, W2, b2, out, E, ntiles);
}